// round 16
// baseline (speedup 1.0000x reference)
#include <cuda_runtime.h>
#include <cuda_fp16.h>
#include <cstdint>
#include <cstddef>

// Problem constants
#define NB 2
#define NP 4096
#define NA 96
#define NF 32
#define NE 20

#define L2E 1.4426950408889634f
#define LN2 0.6931471805599453f

#define THREADS 192       // 6 warps; warp owns 32 rows (2 m16 tiles)
#define TILE_P 2          // 192 rows = 2 p's
#define TILE_ROWS 192

// ---------------- device scratch ----------------
__device__ float g_tgt[NB * NP * NF];    // (srecv@Wt + b1n) * L2E
__device__ float g_src[NB * NA * NF];    // (scalar@Ws) * L2E
__device__ float g_b1e[NF], g_b2e[NF], g_b2n[NF];
// 6 weight matrices [n][k] (B operand, col-major), K padded to 32, fp16:
// 0:w1 hi, 1:w1 lo, 2:w2e hi, 3:w2e lo, 4:w2n hi, 5:w2n lo
__device__ __half g_w[6 * NF * 32];

// ---------------- helpers ----------------
__device__ __forceinline__ float ssp2(float y) {
    float e, t;
    asm("ex2.approx.f32 %0, %1;" : "=f"(e) : "f"(y));
    asm("lg2.approx.f32 %0, %1;" : "=f"(t) : "f"(1.0f + e));
    return t;
}

// fp16 split-2: v = hi + lo, packed as half2 (v0 -> low half)
__device__ __forceinline__ void split2(float v0, float v1,
                                       uint32_t& hi, uint32_t& lo) {
    __half2 h = __floats2half2_rn(v0, v1);
    float f0 = __half2float(__low2half(h));
    float f1 = __half2float(__high2half(h));
    __half2 l = __floats2half2_rn(v0 - f0, v1 - f1);
    hi = *reinterpret_cast<uint32_t*>(&h);
    lo = *reinterpret_cast<uint32_t*>(&l);
}

// m16n8k16 row.col f32.f16.f16.f32
__device__ __forceinline__ void mma16816(float c[4], const uint32_t a[4],
                                         uint32_t b0, uint32_t b1) {
    asm volatile(
        "mma.sync.aligned.m16n8k16.row.col.f32.f16.f16.f32 "
        "{%0,%1,%2,%3}, {%4,%5,%6,%7}, {%8,%9}, {%0,%1,%2,%3};"
        : "+f"(c[0]), "+f"(c[1]), "+f"(c[2]), "+f"(c[3])
        : "r"(a[0]), "r"(a[1]), "r"(a[2]), "r"(a[3]), "r"(b0), "r"(b1));
}

// One GEMM stage for one m-tile: C[16] (4 ntiles x 4) += split-2 product.
// B tiles in smem: matrix m at m*2112 halves, row stride 66 halves.
__device__ __forceinline__ void gemm_mt(const __half* sB, int g, int qr, int qc,
                                        const uint32_t aH0[4], const uint32_t aH1[4],
                                        const uint32_t aL0[4], const uint32_t aL1[4],
                                        float C[16]) {
    #pragma unroll
    for (int nt = 0; nt < 4; nt++) {
        const uint32_t* ph = reinterpret_cast<const uint32_t*>(
            sB + (2 * g)     * 2112 + (nt * 8 + qr) * 66);
        const uint32_t* pl = reinterpret_cast<const uint32_t*>(
            sB + (2 * g + 1) * 2112 + (nt * 8 + qr) * 66);
        uint32_t bh0 = ph[qc], bh1 = ph[qc + 4], bh2 = ph[qc + 8], bh3 = ph[qc + 12];
        uint32_t bl0 = pl[qc], bl1 = pl[qc + 4], bl2 = pl[qc + 8], bl3 = pl[qc + 12];
        float* c = C + nt * 4;
        mma16816(c, aH0, bh0, bh1);   // hi*hi k0-15
        mma16816(c, aH1, bh2, bh3);   // hi*hi k16-31
        mma16816(c, aL0, bh0, bh1);   // lo*hi
        mma16816(c, aL1, bh2, bh3);
        mma16816(c, aH0, bl0, bl1);   // hi*lo
        mma16816(c, aH1, bl2, bl3);
    }
}

// ---------------------------------------------------------------------------
// Precompute: linear terms (scaled L2E), transposed fp16 hi/lo weights, biases
// ---------------------------------------------------------------------------
__global__ void precompute_kernel(const float* __restrict__ scalar,
                                  const float* __restrict__ srecv,
                                  const float* __restrict__ W1n,
                                  const float* __restrict__ b1n,
                                  const float* __restrict__ W1e,
                                  const float* __restrict__ b1e,
                                  const float* __restrict__ W2e,
                                  const float* __restrict__ b2e,
                                  const float* __restrict__ W2n,
                                  const float* __restrict__ b2n)
{
    int gid  = blockIdx.x * blockDim.x + threadIdx.x;
    int gw   = gid >> 5;
    int lane = threadIdx.x & 31;

    if (gid < NF * 32) {                 // (n,k) slot; 3 matrices hi/lo
        int n = gid >> 5, k = gid & 31;
        float w1 = (k < NE) ? W1e[k * NF + n] * L2E : 0.0f;
        float w2 = W2e[k * NF + n] * LN2;
        float w3 = W2n[k * NF + n] * LN2;
        __half h;
        h = __float2half_rn(w1); g_w[0*1024+gid] = h; g_w[1*1024+gid] = __float2half_rn(w1 - __half2float(h));
        h = __float2half_rn(w2); g_w[2*1024+gid] = h; g_w[3*1024+gid] = __float2half_rn(w2 - __half2float(h));
        h = __float2half_rn(w3); g_w[4*1024+gid] = h; g_w[5*1024+gid] = __float2half_rn(w3 - __half2float(h));
    }
    if (gid < NF) {
        g_b1e[gid] = b1e[gid] * L2E;
        float s2e = 0.0f, s2n = 0.0f;
        #pragma unroll
        for (int k = 0; k < NF; k++) { s2e += W2e[k * NF + gid]; s2n += W2n[k * NF + gid]; }
        g_b2e[gid] = b2e[gid] - LN2 * s2e;
        g_b2n[gid] = b2n[gid] - LN2 * s2n;
    }

    if (gw < NB * NP) {
        float xv  = srecv[gw * NF + lane];
        float acc = b1n[lane];
        #pragma unroll
        for (int k = 0; k < NF; k++) {
            float xk = __shfl_sync(0xffffffffu, xv, k);
            acc = fmaf(xk, W1n[(NF + k) * NF + lane], acc);
        }
        g_tgt[gw * NF + lane] = acc * L2E;
    } else if (gw < NB * NP + NB * NA) {
        int r = gw - NB * NP;
        float xv  = scalar[r * NF + lane];
        float acc = 0.0f;
        #pragma unroll
        for (int k = 0; k < NF; k++) {
            float xk = __shfl_sync(0xffffffffu, xv, k);
            acc = fmaf(xk, W1n[k * NF + lane], acc);
        }
        g_src[r * NF + lane] = acc * L2E;
    }
}

// ---------------------------------------------------------------------------
// Dynamic smem layout (bytes):
//  [0, 25344)        B tiles: 6 x (32 rows x 66 halves)
//  [25344, 51456)    red: 192 x 34 floats
//  [51456, 51712)    stgt: 2 x 32 floats
//  [51712, 52480)    sgm: 192 floats
//  [52480, 52608)    b1e | [52608,52736) b2e | [52736,52864) b2n
// ---------------------------------------------------------------------------
#define OFF_RED  25344u
#define OFF_TGT  51456u
#define OFF_GM   51712u
#define OFF_B1E  52480u
#define OFF_B2E  52608u
#define OFF_B2N  52736u
#define DSMEM    52864

extern __shared__ __align__(16) unsigned char smem_raw[];

__global__ __launch_bounds__(THREADS) void main_kernel(
    const float* __restrict__ expansion,
    const float* __restrict__ mask,
    const float* __restrict__ edge,
    float* __restrict__ out)
{
    __half* sB   = reinterpret_cast<__half*>(smem_raw);
    float*  sRED = reinterpret_cast<float*>(smem_raw + OFF_RED);
    float*  sTGT = reinterpret_cast<float*>(smem_raw + OFF_TGT);
    float*  sGM  = reinterpret_cast<float*>(smem_raw + OFF_GM);
    float*  sB1E = reinterpret_cast<float*>(smem_raw + OFF_B1E);
    float*  sB2E = reinterpret_cast<float*>(smem_raw + OFF_B2E);
    float*  sB2N = reinterpret_cast<float*>(smem_raw + OFF_B2N);

    const int t    = threadIdx.x;
    const int w    = t >> 5;
    const int lane = t & 31;
    const int qr   = lane >> 2;     // 0..7
    const int qc   = lane & 3;      // 0..3
    const int tile = blockIdx.x;
    const size_t grow0 = (size_t)tile * TILE_ROWS;

    // ---- stage B tiles (row stride 66 halves), biases, stgt, gm ----
    for (int i = t; i < 6 * 1024; i += THREADS) {
        int m = i >> 10, idx = i & 1023, n = idx >> 5, k = idx & 31;
        sB[m * 2112 + n * 66 + k] = g_w[i];
    }
    if (t < NF) { sB1E[t] = g_b1e[t]; sB2E[t] = g_b2e[t]; sB2N[t] = g_b2n[t]; }
    if (t < TILE_P * NF)
        sTGT[t] = g_tgt[(size_t)(tile * TILE_P + (t >> 5)) * NF + (t & 31)];
    {   // cutoff*mask for own row
        size_t gr = grow0 + t;
        float u;
        asm("ex2.approx.f32 %0, %1;" : "=f"(u)
            : "f"((edge[gr] - 3.5f) * (5.0f * L2E)));
        sGM[t] = __fdividef(mask[gr], 1.0f + u);
    }
    __syncthreads();

    const int b = (int)((grow0) >> 12) >> 5 ? 1 : (tile * TILE_P >= NP ? 1 : 0);
    // simpler & exact: b from bp
    // (bp = tile*TILE_P + p_loc; all rows in CTA share same b since 192 | rows per b)
    const int b_idx = (tile * TILE_P) / NP;

    // ---- per m-tile chain ----
    #pragma unroll 1
    for (int mt = 0; mt < 2; mt++) {
        const int rloc1 = w * 32 + mt * 16 + qr;    // local row (thread's first)
        const int rloc2 = rloc1 + 8;
        const size_t gr1 = grow0 + rloc1;
        const size_t gr2 = grow0 + rloc2;
        const int p_loc = rloc1 / 96;               // same for rloc2
        const int a1 = rloc1 - p_loc * 96;
        const int a2 = a1 + 8;

        // ===== A1: expansion rows -> hi/lo fragments (K=32, zero-padded) =====
        uint32_t aH0[4], aH1[4], aL0[4], aL1[4];
        {
            const float* e1 = expansion + gr1 * NE;
            const float* e2 = expansion + gr2 * NE;
            float2 x10 = *reinterpret_cast<const float2*>(e1 + qc * 2);
            float2 x11 = *reinterpret_cast<const float2*>(e1 + qc * 2 + 8);
            float2 x20 = *reinterpret_cast<const float2*>(e2 + qc * 2);
            float2 x21 = *reinterpret_cast<const float2*>(e2 + qc * 2 + 8);
            float2 x12 = (qc < 2) ? *reinterpret_cast<const float2*>(e1 + qc * 2 + 16)
                                  : make_float2(0.f, 0.f);
            float2 x22 = (qc < 2) ? *reinterpret_cast<const float2*>(e2 + qc * 2 + 16)
                                  : make_float2(0.f, 0.f);
            split2(x10.x, x10.y, aH0[0], aL0[0]);
            split2(x20.x, x20.y, aH0[1], aL0[1]);
            split2(x11.x, x11.y, aH0[2], aL0[2]);
            split2(x21.x, x21.y, aH0[3], aL0[3]);
            split2(x12.x, x12.y, aH1[0], aL1[0]);
            split2(x22.x, x22.y, aH1[1], aL1[1]);
            aH1[2] = aH1[3] = aL1[2] = aL1[3] = 0u;
        }

        // ===== GEMM1: E1pre = X @ W1' =====
        float C[16];
        #pragma unroll
        for (int i = 0; i < 16; i++) C[i] = 0.0f;
        gemm_mt(sB, 0, qr, qc, aH0, aH1, aL0, aL1, C);

        // bias + ssp2 + re-fragment as next A (register-resident chaining)
        #pragma unroll
        for (int ks = 0; ks < 2; ks++) {
            uint32_t* nH = ks ? aH1 : aH0;
            uint32_t* nL = ks ? aL1 : aL0;
            #pragma unroll
            for (int h = 0; h < 2; h++) {
                int nt = 2 * ks + h;
                float* c = C + nt * 4;
                float2 bb = *reinterpret_cast<const float2*>(&sB1E[nt * 8 + qc * 2]);
                float v0 = ssp2(c[0] + bb.x), v1 = ssp2(c[1] + bb.y);
                float v2 = ssp2(c[2] + bb.x), v3 = ssp2(c[3] + bb.y);
                split2(v0, v1, nH[2 * h + 0], nL[2 * h + 0]);   // rows t/4
                split2(v2, v3, nH[2 * h + 1], nL[2 * h + 1]);   // rows t/4+8
            }
        }

        // ===== GEMM2: gates = E1 @ W2e' =====
        float gate[16];
        #pragma unroll
        for (int i = 0; i < 16; i++) C[i] = 0.0f;
        gemm_mt(sB, 1, qr, qc, aH0, aH1, aL0, aL1, C);
        #pragma unroll
        for (int nt = 0; nt < 4; nt++) {
            float2 bb = *reinterpret_cast<const float2*>(&sB2E[nt * 8 + qc * 2]);
            gate[nt * 4 + 0] = C[nt * 4 + 0] + bb.x;
            gate[nt * 4 + 1] = C[nt * 4 + 1] + bb.y;
            gate[nt * 4 + 2] = C[nt * 4 + 2] + bb.x;
            gate[nt * 4 + 3] = C[nt * 4 + 3] + bb.y;
        }

        // ===== A3: ssp2(src + tgt) fragments =====
        #pragma unroll
        for (int ks = 0; ks < 2; ks++) {
            uint32_t* nH = ks ? aH1 : aH0;
            uint32_t* nL = ks ? aL1 : aL0;
            #pragma unroll
            for (int h = 0; h < 2; h++) {
                int colb = (2 * ks + h) * 8 + qc * 2;
                float2 s1 = *reinterpret_cast<const float2*>(
                    g_src + ((size_t)b_idx * NA + a1) * NF + colb);
                float2 s2 = *reinterpret_cast<const float2*>(
                    g_src + ((size_t)b_idx * NA + a2) * NF + colb);
                float2 tg = *reinterpret_cast<const float2*>(&sTGT[p_loc * NF + colb]);
                float v0 = ssp2(s1.x + tg.x), v1 = ssp2(s1.y + tg.y);
                float v2 = ssp2(s2.x + tg.x), v3 = ssp2(s2.y + tg.y);
                split2(v0, v1, nH[2 * h + 0], nL[2 * h + 0]);
                split2(v2, v3, nH[2 * h + 1], nL[2 * h + 1]);
            }
        }

        // ===== GEMM3: nodes = N1 @ W2n' =====
        #pragma unroll
        for (int i = 0; i < 16; i++) C[i] = 0.0f;
        gemm_mt(sB, 2, qr, qc, aH0, aH1, aL0, aL1, C);

        // r = gm * gate * node -> red buffer (stride 34, float2 per pair)
        float gm1 = sGM[rloc1], gm2 = sGM[rloc2];
        #pragma unroll
        for (int nt = 0; nt < 4; nt++) {
            int colb = nt * 8 + qc * 2;
            float2 bb = *reinterpret_cast<const float2*>(&sB2N[colb]);
            float2 r1, r2;
            r1.x = gm1 * gate[nt * 4 + 0] * (C[nt * 4 + 0] + bb.x);
            r1.y = gm1 * gate[nt * 4 + 1] * (C[nt * 4 + 1] + bb.y);
            r2.x = gm2 * gate[nt * 4 + 2] * (C[nt * 4 + 2] + bb.x);
            r2.y = gm2 * gate[nt * 4 + 3] * (C[nt * 4 + 3] + bb.y);
            *reinterpret_cast<float2*>(&sRED[rloc1 * 34 + colb]) = r1;
            *reinterpret_cast<float2*>(&sRED[rloc2 * 34 + colb]) = r2;
        }
    }

    __syncthreads();

    // ---- reduce 96 rows per p, write output ----
    if (t < TILE_P * NF) {
        int p = t >> 5, f = t & 31;
        float s = 0.0f;
        #pragma unroll
        for (int r = 0; r < 96; r++) s += sRED[(p * 96 + r) * 34 + f];
        out[(size_t)(tile * TILE_P + p) * NF + f] = s;
    }
}

// ---------------------------------------------------------------------------
// Launch: 2 graph nodes (precompute, main)
// ---------------------------------------------------------------------------
extern "C" void kernel_launch(void* const* d_in, const int* in_sizes, int n_in,
                              void* d_out, int out_size)
{
    const float* scalar    = (const float*)d_in[0];
    const float* srecv     = (const float*)d_in[1];
    const float* expansion = (const float*)d_in[2];
    const float* mask      = (const float*)d_in[3];
    const float* edge      = (const float*)d_in[4];
    const float* W1e       = (const float*)d_in[5];
    const float* b1e       = (const float*)d_in[6];
    const float* W2e       = (const float*)d_in[7];
    const float* b2e       = (const float*)d_in[8];
    const float* W1n       = (const float*)d_in[9];
    const float* b1n       = (const float*)d_in[10];
    const float* W2n       = (const float*)d_in[11];
    const float* b2n       = (const float*)d_in[12];
    float* out = (float*)d_out;

    cudaFuncSetAttribute(main_kernel,
                         cudaFuncAttributeMaxDynamicSharedMemorySize, DSMEM);

    int rows    = NB * NP + NB * NA;
    int threads = 256;
    int blocks  = (rows * 32 + threads - 1) / threads;
    precompute_kernel<<<blocks, threads>>>(scalar, srecv, W1n, b1n,
                                           W1e, b1e, W2e, b2e, W2n, b2n);

    main_kernel<<<NB * NP / TILE_P, THREADS, DSMEM>>>(expansion, mask, edge, out);
}

// round 17
// speedup vs baseline: 1.6455x; 1.6455x over previous
#include <cuda_runtime.h>
#include <cuda_fp16.h>
#include <cstdint>
#include <cstddef>

// Problem constants
#define NB 2
#define NP 4096
#define NA 96
#define NF 32
#define NE 20

#define L2E 1.4426950408889634f
#define LN2 0.6931471805599453f

#define THREADS 192       // 6 warps; warp owns 32 rows (2 m16 tiles)
#define TILE_P 2          // 192 rows = 2 p's
#define TILE_ROWS 192

// B tile geometry: row stride 72 halves (36 words) -> conflict-free lane banks
#define BSTRIDE 72
#define BMAT    (32 * BSTRIDE)   // 2304 halves per matrix

// ---------------- device scratch ----------------
__device__ float g_tgt[NB * NP * NF];    // (srecv@Wt + b1n) * L2E
__device__ float g_src[NB * NA * NF];    // (scalar@Ws) * L2E
__device__ float g_b1e[NF], g_b2e[NF], g_b2n[NF];
// 6 weight matrices [n][k] (B operand, col-major), K padded to 32, fp16:
// 0:w1 hi, 1:w1 lo, 2:w2e hi, 3:w2e lo, 4:w2n hi, 5:w2n lo
__device__ __half g_w[6 * NF * 32];

// ---------------- helpers ----------------
__device__ __forceinline__ float ssp2(float y) {
    float e, t;
    asm("ex2.approx.f32 %0, %1;" : "=f"(e) : "f"(y));
    asm("lg2.approx.f32 %0, %1;" : "=f"(t) : "f"(1.0f + e));
    return t;
}

// fp16 split-2: v = hi + lo, packed as half2 (v0 -> low half)
__device__ __forceinline__ void split2(float v0, float v1,
                                       uint32_t& hi, uint32_t& lo) {
    __half2 h = __floats2half2_rn(v0, v1);
    float f0 = __half2float(__low2half(h));
    float f1 = __half2float(__high2half(h));
    __half2 l = __floats2half2_rn(v0 - f0, v1 - f1);
    hi = *reinterpret_cast<uint32_t*>(&h);
    lo = *reinterpret_cast<uint32_t*>(&l);
}

// m16n8k16 row.col f32.f16.f16.f32
__device__ __forceinline__ void mma16816(float c[4], const uint32_t a[4],
                                         uint32_t b0, uint32_t b1) {
    asm volatile(
        "mma.sync.aligned.m16n8k16.row.col.f32.f16.f16.f32 "
        "{%0,%1,%2,%3}, {%4,%5,%6,%7}, {%8,%9}, {%0,%1,%2,%3};"
        : "+f"(c[0]), "+f"(c[1]), "+f"(c[2]), "+f"(c[3])
        : "r"(a[0]), "r"(a[1]), "r"(a[2]), "r"(a[3]), "r"(b0), "r"(b1));
}

// One GEMM stage for one m-tile: C[16] (4 ntiles x 4) += split-2 product.
__device__ __forceinline__ void gemm_mt(const __half* sB, int g, int qr, int qc,
                                        const uint32_t aH0[4], const uint32_t aH1[4],
                                        const uint32_t aL0[4], const uint32_t aL1[4],
                                        float C[16]) {
    #pragma unroll
    for (int nt = 0; nt < 4; nt++) {
        const uint32_t* ph = reinterpret_cast<const uint32_t*>(
            sB + (2 * g)     * BMAT + (nt * 8 + qr) * BSTRIDE);
        const uint32_t* pl = reinterpret_cast<const uint32_t*>(
            sB + (2 * g + 1) * BMAT + (nt * 8 + qr) * BSTRIDE);
        uint32_t bh0 = ph[qc], bh1 = ph[qc + 4], bh2 = ph[qc + 8], bh3 = ph[qc + 12];
        uint32_t bl0 = pl[qc], bl1 = pl[qc + 4], bl2 = pl[qc + 8], bl3 = pl[qc + 12];
        float* c = C + nt * 4;
        mma16816(c, aH0, bh0, bh1);   // hi*hi k0-15
        mma16816(c, aH1, bh2, bh3);   // hi*hi k16-31
        mma16816(c, aL0, bh0, bh1);   // lo*hi
        mma16816(c, aL1, bh2, bh3);
        mma16816(c, aH0, bl0, bl1);   // hi*lo
        mma16816(c, aH1, bl2, bl3);
    }
}

// ---------------------------------------------------------------------------
// Precompute: linear terms (scaled L2E), transposed fp16 hi/lo weights, biases
// ---------------------------------------------------------------------------
__global__ void precompute_kernel(const float* __restrict__ scalar,
                                  const float* __restrict__ srecv,
                                  const float* __restrict__ W1n,
                                  const float* __restrict__ b1n,
                                  const float* __restrict__ W1e,
                                  const float* __restrict__ b1e,
                                  const float* __restrict__ W2e,
                                  const float* __restrict__ b2e,
                                  const float* __restrict__ W2n,
                                  const float* __restrict__ b2n)
{
    int gid  = blockIdx.x * blockDim.x + threadIdx.x;
    int gw   = gid >> 5;
    int lane = threadIdx.x & 31;

    if (gid < NF * 32) {                 // (n,k) slot; 3 matrices hi/lo
        int n = gid >> 5, k = gid & 31;
        float w1 = (k < NE) ? W1e[k * NF + n] * L2E : 0.0f;
        float w2 = W2e[k * NF + n] * LN2;
        float w3 = W2n[k * NF + n] * LN2;
        __half h;
        h = __float2half_rn(w1); g_w[0*1024+gid] = h; g_w[1*1024+gid] = __float2half_rn(w1 - __half2float(h));
        h = __float2half_rn(w2); g_w[2*1024+gid] = h; g_w[3*1024+gid] = __float2half_rn(w2 - __half2float(h));
        h = __float2half_rn(w3); g_w[4*1024+gid] = h; g_w[5*1024+gid] = __float2half_rn(w3 - __half2float(h));
    }
    if (gid < NF) {
        g_b1e[gid] = b1e[gid] * L2E;
        float s2e = 0.0f, s2n = 0.0f;
        #pragma unroll
        for (int k = 0; k < NF; k++) { s2e += W2e[k * NF + gid]; s2n += W2n[k * NF + gid]; }
        g_b2e[gid] = b2e[gid] - LN2 * s2e;
        g_b2n[gid] = b2n[gid] - LN2 * s2n;
    }

    if (gw < NB * NP) {
        float xv  = srecv[gw * NF + lane];
        float acc = b1n[lane];
        #pragma unroll
        for (int k = 0; k < NF; k++) {
            float xk = __shfl_sync(0xffffffffu, xv, k);
            acc = fmaf(xk, W1n[(NF + k) * NF + lane], acc);
        }
        g_tgt[gw * NF + lane] = acc * L2E;
    } else if (gw < NB * NP + NB * NA) {
        int r = gw - NB * NP;
        float xv  = scalar[r * NF + lane];
        float acc = 0.0f;
        #pragma unroll
        for (int k = 0; k < NF; k++) {
            float xk = __shfl_sync(0xffffffffu, xv, k);
            acc = fmaf(xk, W1n[k * NF + lane], acc);
        }
        g_src[r * NF + lane] = acc * L2E;
    }
}

// ---------------------------------------------------------------------------
// Dynamic smem layout (bytes):
//  [0, 27648)          B tiles: 6 x (32 rows x 72 halves)
//  [27648, 28416)      warp partials: 6 x 32 floats
//  [28416, 28672)      stgt: 2 x 32 floats
//  [28672, 29440)      sgm: 192 floats
//  [29440,29568) b1e | [29568,29696) b2e | [29696,29824) b2n
// ---------------------------------------------------------------------------
#define OFF_WP   27648u
#define OFF_TGT  28416u
#define OFF_GM   28672u
#define OFF_B1E  29440u
#define OFF_B2E  29568u
#define OFF_B2N  29696u
#define DSMEM    29824

extern __shared__ __align__(16) unsigned char smem_raw[];

__global__ __launch_bounds__(THREADS) void main_kernel(
    const float* __restrict__ expansion,
    const float* __restrict__ mask,
    const float* __restrict__ edge,
    float* __restrict__ out)
{
    __half* sB   = reinterpret_cast<__half*>(smem_raw);
    float*  sWP  = reinterpret_cast<float*>(smem_raw + OFF_WP);
    float*  sTGT = reinterpret_cast<float*>(smem_raw + OFF_TGT);
    float*  sGM  = reinterpret_cast<float*>(smem_raw + OFF_GM);
    float*  sB1E = reinterpret_cast<float*>(smem_raw + OFF_B1E);
    float*  sB2E = reinterpret_cast<float*>(smem_raw + OFF_B2E);
    float*  sB2N = reinterpret_cast<float*>(smem_raw + OFF_B2N);

    const int t    = threadIdx.x;
    const int w    = t >> 5;
    const int lane = t & 31;
    const int qr   = lane >> 2;     // 0..7
    const int qc   = lane & 3;      // 0..3
    const int tile = blockIdx.x;
    const size_t grow0 = (size_t)tile * TILE_ROWS;
    const int b_idx = (tile * TILE_P) / NP;

    // ---- stage B tiles (stride 72 halves), biases, stgt, gm ----
    for (int i = t; i < 6 * 1024; i += THREADS) {
        int m = i >> 10, idx = i & 1023, n = idx >> 5, k = idx & 31;
        sB[m * BMAT + n * BSTRIDE + k] = g_w[i];
    }
    if (t < NF) { sB1E[t] = g_b1e[t]; sB2E[t] = g_b2e[t]; sB2N[t] = g_b2n[t]; }
    if (t < TILE_P * NF)
        sTGT[t] = g_tgt[(size_t)(tile * TILE_P + (t >> 5)) * NF + (t & 31)];
    {   // cutoff*mask for own row
        size_t gr = grow0 + t;
        float u;
        asm("ex2.approx.f32 %0, %1;" : "=f"(u)
            : "f"((edge[gr] - 3.5f) * (5.0f * L2E)));
        sGM[t] = __fdividef(mask[gr], 1.0f + u);
    }
    __syncthreads();

    // per-thread column accumulators: s[nt*2+j] = sum over this warp's rows
    // of gm*gate*node at column nt*8 + qc*2 + j
    float s[8];
    #pragma unroll
    for (int i = 0; i < 8; i++) s[i] = 0.0f;

    // ---- per m-tile chain ----
    #pragma unroll 1
    for (int mt = 0; mt < 2; mt++) {
        const int rloc1 = w * 32 + mt * 16 + qr;    // thread's first local row
        const int rloc2 = rloc1 + 8;
        const size_t gr1 = grow0 + rloc1;
        const size_t gr2 = grow0 + rloc2;
        const int p_loc = rloc1 / 96;               // same for rloc2 (and whole warp)
        const int a1 = rloc1 - p_loc * 96;
        const int a2 = a1 + 8;

        // ===== A1: expansion rows -> hi/lo fragments (K=32, zero-padded) =====
        uint32_t aH0[4], aH1[4], aL0[4], aL1[4];
        {
            const float* e1 = expansion + gr1 * NE;
            const float* e2 = expansion + gr2 * NE;
            float2 x10 = *reinterpret_cast<const float2*>(e1 + qc * 2);
            float2 x11 = *reinterpret_cast<const float2*>(e1 + qc * 2 + 8);
            float2 x20 = *reinterpret_cast<const float2*>(e2 + qc * 2);
            float2 x21 = *reinterpret_cast<const float2*>(e2 + qc * 2 + 8);
            float2 x12 = (qc < 2) ? *reinterpret_cast<const float2*>(e1 + qc * 2 + 16)
                                  : make_float2(0.f, 0.f);
            float2 x22 = (qc < 2) ? *reinterpret_cast<const float2*>(e2 + qc * 2 + 16)
                                  : make_float2(0.f, 0.f);
            split2(x10.x, x10.y, aH0[0], aL0[0]);
            split2(x20.x, x20.y, aH0[1], aL0[1]);
            split2(x11.x, x11.y, aH0[2], aL0[2]);
            split2(x21.x, x21.y, aH0[3], aL0[3]);
            split2(x12.x, x12.y, aH1[0], aL1[0]);
            split2(x22.x, x22.y, aH1[1], aL1[1]);
            aH1[2] = aH1[3] = aL1[2] = aL1[3] = 0u;
        }

        // ===== GEMM1: E1pre = X @ W1' =====
        float C[16];
        #pragma unroll
        for (int i = 0; i < 16; i++) C[i] = 0.0f;
        gemm_mt(sB, 0, qr, qc, aH0, aH1, aL0, aL1, C);

        // bias + ssp2 + re-fragment as next A (register-resident chaining)
        #pragma unroll
        for (int ks = 0; ks < 2; ks++) {
            uint32_t* nH = ks ? aH1 : aH0;
            uint32_t* nL = ks ? aL1 : aL0;
            #pragma unroll
            for (int h = 0; h < 2; h++) {
                int nt = 2 * ks + h;
                float* c = C + nt * 4;
                float2 bb = *reinterpret_cast<const float2*>(&sB1E[nt * 8 + qc * 2]);
                float v0 = ssp2(c[0] + bb.x), v1 = ssp2(c[1] + bb.y);
                float v2 = ssp2(c[2] + bb.x), v3 = ssp2(c[3] + bb.y);
                split2(v0, v1, nH[2 * h + 0], nL[2 * h + 0]);   // rows qr
                split2(v2, v3, nH[2 * h + 1], nL[2 * h + 1]);   // rows qr+8
            }
        }

        // ===== GEMM2: gates = E1 @ W2e' =====
        float gate[16];
        #pragma unroll
        for (int i = 0; i < 16; i++) C[i] = 0.0f;
        gemm_mt(sB, 1, qr, qc, aH0, aH1, aL0, aL1, C);
        #pragma unroll
        for (int nt = 0; nt < 4; nt++) {
            float2 bb = *reinterpret_cast<const float2*>(&sB2E[nt * 8 + qc * 2]);
            gate[nt * 4 + 0] = C[nt * 4 + 0] + bb.x;
            gate[nt * 4 + 1] = C[nt * 4 + 1] + bb.y;
            gate[nt * 4 + 2] = C[nt * 4 + 2] + bb.x;
            gate[nt * 4 + 3] = C[nt * 4 + 3] + bb.y;
        }

        // ===== A3: ssp2(src + tgt) fragments =====
        #pragma unroll
        for (int ks = 0; ks < 2; ks++) {
            uint32_t* nH = ks ? aH1 : aH0;
            uint32_t* nL = ks ? aL1 : aL0;
            #pragma unroll
            for (int h = 0; h < 2; h++) {
                int colb = (2 * ks + h) * 8 + qc * 2;
                float2 s1 = *reinterpret_cast<const float2*>(
                    g_src + ((size_t)b_idx * NA + a1) * NF + colb);
                float2 s2 = *reinterpret_cast<const float2*>(
                    g_src + ((size_t)b_idx * NA + a2) * NF + colb);
                float2 tg = *reinterpret_cast<const float2*>(&sTGT[p_loc * NF + colb]);
                float v0 = ssp2(s1.x + tg.x), v1 = ssp2(s1.y + tg.y);
                float v2 = ssp2(s2.x + tg.x), v3 = ssp2(s2.y + tg.y);
                split2(v0, v1, nH[2 * h + 0], nL[2 * h + 0]);
                split2(v2, v3, nH[2 * h + 1], nL[2 * h + 1]);
            }
        }

        // ===== GEMM3: nodes = N1 @ W2n' =====
        #pragma unroll
        for (int i = 0; i < 16; i++) C[i] = 0.0f;
        gemm_mt(sB, 2, qr, qc, aH0, aH1, aL0, aL1, C);

        // accumulate gm * gate * node into per-column register sums
        float gm1 = sGM[rloc1], gm2 = sGM[rloc2];
        #pragma unroll
        for (int nt = 0; nt < 4; nt++) {
            float2 bb = *reinterpret_cast<const float2*>(&sB2N[nt * 8 + qc * 2]);
            s[nt * 2 + 0] += gm1 * gate[nt * 4 + 0] * (C[nt * 4 + 0] + bb.x)
                           + gm2 * gate[nt * 4 + 2] * (C[nt * 4 + 2] + bb.x);
            s[nt * 2 + 1] += gm1 * gate[nt * 4 + 1] * (C[nt * 4 + 1] + bb.y)
                           + gm2 * gate[nt * 4 + 3] * (C[nt * 4 + 3] + bb.y);
        }
    }

    // ---- warp-level reduction over qr lanes (rows) ----
    #pragma unroll
    for (int m = 4; m <= 16; m <<= 1) {
        #pragma unroll
        for (int i = 0; i < 8; i++)
            s[i] += __shfl_xor_sync(0xffffffffu, s[i], m);
    }
    if (qr == 0) {   // lanes 0..3 hold full warp-column sums
        #pragma unroll
        for (int nt = 0; nt < 4; nt++)
            *reinterpret_cast<float2*>(&sWP[w * 32 + nt * 8 + qc * 2]) =
                make_float2(s[nt * 2 + 0], s[nt * 2 + 1]);
    }
    __syncthreads();

    // ---- combine 3 warp partials per p, write output ----
    if (t < TILE_P * NF) {
        int p = t >> 5, f = t & 31;
        float sum = sWP[(3 * p + 0) * 32 + f]
                  + sWP[(3 * p + 1) * 32 + f]
                  + sWP[(3 * p + 2) * 32 + f];
        out[(size_t)(tile * TILE_P + p) * NF + f] = sum;
    }
}

// ---------------------------------------------------------------------------
// Launch: 2 graph nodes (precompute, main)
// ---------------------------------------------------------------------------
extern "C" void kernel_launch(void* const* d_in, const int* in_sizes, int n_in,
                              void* d_out, int out_size)
{
    const float* scalar    = (const float*)d_in[0];
    const float* srecv     = (const float*)d_in[1];
    const float* expansion = (const float*)d_in[2];
    const float* mask      = (const float*)d_in[3];
    const float* edge      = (const float*)d_in[4];
    const float* W1e       = (const float*)d_in[5];
    const float* b1e       = (const float*)d_in[6];
    const float* W2e       = (const float*)d_in[7];
    const float* b2e       = (const float*)d_in[8];
    const float* W1n       = (const float*)d_in[9];
    const float* b1n       = (const float*)d_in[10];
    const float* W2n       = (const float*)d_in[11];
    const float* b2n       = (const float*)d_in[12];
    float* out = (float*)d_out;

    int rows    = NB * NP + NB * NA;
    int threads = 256;
    int blocks  = (rows * 32 + threads - 1) / threads;
    precompute_kernel<<<blocks, threads>>>(scalar, srecv, W1n, b1n,
                                           W1e, b1e, W2e, b2e, W2n, b2n);

    main_kernel<<<NB * NP / TILE_P, THREADS, DSMEM>>>(expansion, mask, edge, out);
}